// round 3
// baseline (speedup 1.0000x reference)
#include <cuda_runtime.h>
#include <cuda_bf16.h>

// Problem constants (fixed by the dataset): B=4, I=64, O=64, K=3, H=W=512.
#define EPS_F 1e-8f

// Scratch for modulated+demodulated weights, layout [b][i][o][k] (k = ky*3+kx)
// so the conv kernel can stream 576 contiguous floats per (b, i).
// 4*64*64*9 floats = 2.36 MB -> stays L2-resident across the conv kernel.
__device__ float g_wmod[4 * 64 * 64 * 9];

// ---------------------------------------------------------------------------
// Kernel 1: per-(b,o) style modulation + demodulation.
// w[b,o,i,k] = weight[o,i,k] * style[b,i];  sigma = sqrt(EPS + sum w^2)
// g_wmod[b,i,o,k] = w / sigma
// One block per (b,o): 256 blocks x 256 threads. Negligible cost (~5 us).
// ---------------------------------------------------------------------------
__global__ void modulate_kernel(const float* __restrict__ weight,   // (O, I, 3, 3)
                                const float* __restrict__ style) {  // (B, I)
    const int bo  = blockIdx.x;
    const int b   = bo >> 6;
    const int o   = bo & 63;
    const int tid = threadIdx.x;

    __shared__ float red[8];
    __shared__ float s_inv;

    float sum = 0.f;
    for (int idx = tid; idx < 576; idx += 256) {
        const int i = idx / 9;
        const float v = weight[o * 576 + idx] * style[b * 64 + i];
        sum += v * v;
    }
    #pragma unroll
    for (int off = 16; off; off >>= 1)
        sum += __shfl_down_sync(0xffffffffu, sum, off);
    if ((tid & 31) == 0) red[tid >> 5] = sum;
    __syncthreads();
    if (tid == 0) {
        float t = 0.f;
        #pragma unroll
        for (int k = 0; k < 8; k++) t += red[k];
        s_inv = rsqrtf(EPS_F + t);
    }
    __syncthreads();
    const float inv = s_inv;

    for (int idx = tid; idx < 576; idx += 256) {
        const int i = idx / 9;
        const int k = idx - i * 9;
        const float v = weight[o * 576 + idx] * style[b * 64 + i] * inv;
        g_wmod[((b * 64 + i) * 64 + o) * 9 + k] = v;
    }
}

// ---------------------------------------------------------------------------
// Kernel 2: direct 3x3 conv, one block per (b, 16x16 output tile), all 64
// output channels computed in-block (input tile read once per block).
//
// Thread layout (256 threads = 8 warps):
//   warp  (tid>>5)   -> o-group: output channels [wid*8, wid*8+8)
//                       => weight smem reads are warp-uniform broadcasts
//   lane  (tid&31)   -> pgy = lane>>1 (pixel row 0..15),
//                       cbase = (lane&1)*8 (pixel cols cbase..cbase+7)
//
// Per input channel i: 576 FFMA vs ~102 LDS per thread -> FMA-pipe bound.
// ---------------------------------------------------------------------------
__global__ __launch_bounds__(256, 2)
void conv_kernel(const float* __restrict__ input,   // (B, I, 512, 512)
                 float* __restrict__ out) {         // (B, O, 512, 512)
    __shared__ float s_in[18 * 18];   // input tile + 1-px halo (stride 18: <=2-way conflicts)
    __shared__ float s_w[64 * 9];     // all 64 output-channel filters for channel i

    const int tid   = threadIdx.x;
    const int b     = blockIdx.z;
    const int h0    = blockIdx.y << 4;
    const int w0    = blockIdx.x << 4;
    const int wid   = tid >> 5;          // o-group
    const int lane  = tid & 31;
    const int pgy   = lane >> 1;         // pixel row in tile
    const int cbase = (lane & 1) << 3;   // pixel col base in tile

    float acc[8][8];
    #pragma unroll
    for (int o = 0; o < 8; o++)
        #pragma unroll
        for (int x = 0; x < 8; x++) acc[o][x] = 0.f;

    const float* in_b = input + (size_t)b * 64 * 512 * 512;
    const float* wm_b = g_wmod + (size_t)b * 64 * 64 * 9;

    for (int i = 0; i < 64; i++) {
        __syncthreads();  // protect smem from previous iteration's readers

        // --- load 18x18 input tile (zero-padded at image border) ---
        const float* in_c = in_b + (size_t)i * 512 * 512;
        for (int idx = tid; idx < 324; idx += 256) {
            const int r  = idx / 18;
            const int c  = idx - r * 18;
            const int gh = h0 + r - 1;
            const int gw = w0 + c - 1;
            float v = 0.f;
            if ((unsigned)gh < 512u && (unsigned)gw < 512u)
                v = in_c[gh * 512 + gw];
            s_in[idx] = v;
        }
        // --- load 64x9 modulated weights for channel i ---
        const float* wsrc = wm_b + (size_t)i * 64 * 9;
        for (int idx = tid; idx < 576; idx += 256)
            s_w[idx] = wsrc[idx];

        __syncthreads();

        // --- hoist 3x10 input neighborhood to registers ---
        float v[3][10];
        #pragma unroll
        for (int dy = 0; dy < 3; dy++)
            #pragma unroll
            for (int c = 0; c < 10; c++)
                v[dy][c] = s_in[(pgy + dy) * 18 + cbase + c];

        // --- 8 o-channels x 8 pixels x 9 taps = 576 FFMA ---
        #pragma unroll
        for (int o = 0; o < 8; o++) {
            float wr[9];
            const float* wp = s_w + ((wid << 3) + o) * 9;   // warp-uniform -> LDS broadcast
            #pragma unroll
            for (int k = 0; k < 9; k++) wr[k] = wp[k];
            #pragma unroll
            for (int x = 0; x < 8; x++) {
                float a = acc[o][x];
                #pragma unroll
                for (int dy = 0; dy < 3; dy++)
                    #pragma unroll
                    for (int dx = 0; dx < 3; dx++)
                        a += wr[dy * 3 + dx] * v[dy][x + dx];
                acc[o][x] = a;
            }
        }
    }

    // --- vectorized stores: 2x STG.128 per o-channel ---
    const int hh = h0 + pgy;
    float* obase = out + ((size_t)b * 64 + (wid << 3)) * (512 * 512)
                       + (size_t)hh * 512 + w0 + cbase;
    #pragma unroll
    for (int o = 0; o < 8; o++) {
        float4 lo = make_float4(acc[o][0], acc[o][1], acc[o][2], acc[o][3]);
        float4 hi = make_float4(acc[o][4], acc[o][5], acc[o][6], acc[o][7]);
        float4* p = reinterpret_cast<float4*>(obase + (size_t)o * 512 * 512);
        p[0] = lo;
        p[1] = hi;
    }
}

// ---------------------------------------------------------------------------
// Harness entry point.
//   d_in[0] = input  (4, 64, 512, 512) float
//   d_in[1] = style  (4, 64)           float
//   d_in[2] = weight (64, 64, 3, 3)    float
//   d_out   = (4, 64, 512, 512) float
// ---------------------------------------------------------------------------
extern "C" void kernel_launch(void* const* d_in, const int* in_sizes, int n_in,
                              void* d_out, int out_size) {
    const float* input  = (const float*)d_in[0];
    const float* style  = (const float*)d_in[1];
    const float* weight = (const float*)d_in[2];
    float* out = (float*)d_out;

    modulate_kernel<<<256, 256>>>(weight, style);

    dim3 grid(512 / 16, 512 / 16, 4);   // (32, 32, 4)
    conv_kernel<<<grid, 256>>>(input, out);
}

// round 5
// speedup vs baseline: 6.4369x; 6.4369x over previous
#include <cuda_runtime.h>
#include <cuda_fp16.h>
#include <cstdint>
#include <cstddef>

// Problem constants: B=4, I=64, O=64, K=3, H=W=512.
#define EPS_F 1e-8f

// ---------------------------------------------------------------------------
// Device scratch (static device arrays only; no runtime alloc).
// ---------------------------------------------------------------------------
// Input transposed to HWC fp16: g_hwc[b][y][x][i], 128 B per pixel.
__device__ __align__(16) __half g_hwc[(size_t)4 * 512 * 512 * 64];   // 128 MB
// Modulated weights, B-operand layout for mma.sync:
// g_wB[b][kpair][o] : uint32 = half2( w[k=2*kpair], w[k=2*kpair+1] ),
// k = tap*64 + i, kpair = tap*32 + i/2. 288 rows x 64 cols per sample.
__device__ __align__(16) uint32_t g_wB[4 * 288 * 64];                // 294 KB

__device__ __forceinline__ uint32_t smem_u32(const void* p) {
    uint32_t a;
    asm("{ .reg .u64 t; cvta.to.shared.u64 t, %1; cvt.u32.u64 %0, t; }"
        : "=r"(a) : "l"(p));
    return a;
}

// ---------------------------------------------------------------------------
// Kernel 1: modulate + demodulate -> fp16 B-operand tiles.
// ---------------------------------------------------------------------------
__global__ void modulate_kernel(const float* __restrict__ weight,   // (O=64, I=64, 3, 3)
                                const float* __restrict__ style) {  // (B=4, I=64)
    const int bo  = blockIdx.x;
    const int b   = bo >> 6;
    const int o   = bo & 63;
    const int tid = threadIdx.x;

    __shared__ float red[8];
    __shared__ float s_inv;

    float sum = 0.f;
    for (int idx = tid; idx < 576; idx += 256) {
        const int i = idx / 9;
        const float v = weight[o * 576 + idx] * style[b * 64 + i];
        sum += v * v;
    }
    #pragma unroll
    for (int off = 16; off; off >>= 1)
        sum += __shfl_down_sync(0xffffffffu, sum, off);
    if ((tid & 31) == 0) red[tid >> 5] = sum;
    __syncthreads();
    if (tid == 0) {
        float t = 0.f;
        #pragma unroll
        for (int k = 0; k < 8; k++) t += red[k];
        s_inv = rsqrtf(EPS_F + t);
    }
    __syncthreads();
    const float inv = s_inv;

    // 288 (ipair, tap) entries -> g_wB[b][tap*32 + ipair][o]
    for (int idx = tid; idx < 288; idx += 256) {
        const int ip  = idx / 9;
        const int tap = idx - ip * 9;
        const int i0  = 2 * ip;
        const float v0 = weight[o * 576 + i0 * 9 + tap]       * style[b * 64 + i0]     * inv;
        const float v1 = weight[o * 576 + (i0 + 1) * 9 + tap] * style[b * 64 + i0 + 1] * inv;
        __half2 h = __floats2half2_rn(v0, v1);
        g_wB[(size_t)b * 18432 + (size_t)(tap * 32 + ip) * 64 + o] =
            *reinterpret_cast<uint32_t*>(&h);
    }
}

// ---------------------------------------------------------------------------
// Kernel 2: NCHW fp32 -> HWC fp16 transpose.
// ---------------------------------------------------------------------------
__global__ __launch_bounds__(256)
void transpose_kernel(const float* __restrict__ input) {  // (4, 64, 512, 512)
    __shared__ float s[64][129];
    const int tid = threadIdx.x;
    const int b   = blockIdx.z;
    const int y   = blockIdx.y;
    const int x0  = blockIdx.x << 7;

    #pragma unroll
    for (int it = 0; it < 32; it++) {
        const int idx = it * 256 + tid;
        const int i  = idx >> 7;
        const int xx = idx & 127;
        s[i][xx] = input[((size_t)(b * 64 + i) * 512 + y) * 512 + x0 + xx];
    }
    __syncthreads();

    const int x = tid >> 1;
    const int h = tid & 1;          // channel half: [h*32, h*32+32)
    uint32_t pk[16];
    #pragma unroll
    for (int j = 0; j < 16; j++) {
        __half2 hh = __floats2half2_rn(s[h * 32 + 2 * j][x], s[h * 32 + 2 * j + 1][x]);
        pk[j] = *reinterpret_cast<uint32_t*>(&hh);
    }
    __half* dst = g_hwc + ((size_t)(b * 512 + y) * 512 + x0 + x) * 64 + h * 32;
    uint4* d4 = reinterpret_cast<uint4*>(dst);
    #pragma unroll
    for (int j = 0; j < 4; j++)
        d4[j] = make_uint4(pk[4*j], pk[4*j+1], pk[4*j+2], pk[4*j+3]);
}

// ---------------------------------------------------------------------------
// Kernel 3: fp16 mma.sync implicit-GEMM conv.
// CTA: 256 threads, output tile 8 rows x 16 cols (M=128 px), N=64, K=576.
// A: 10x18 halo tile, HWC fp16, pixel stride 72 halves (144 B) in smem.
// B: [288 kpair][72-padded o] uint32 in smem (bank-conflict-free).
// Warp (wm = wid&3, wn = wid>>2): m32 (tile rows 2wm,2wm+1) x n32 (o base wn*32).
// ---------------------------------------------------------------------------
static constexpr int ASH_BYTES = 180 * 144;          // 25920
static constexpr int BSH_BYTES = 288 * 72 * 4;       // 82944
static constexpr int CONV_SMEM = ASH_BYTES + BSH_BYTES;   // 108864

__global__ __launch_bounds__(256, 2)
void conv_kernel(float* __restrict__ out) {          // (4, 64, 512, 512)
    extern __shared__ __align__(16) char dsm[];
    __half*    Ash = reinterpret_cast<__half*>(dsm);
    uint32_t*  Bsh = reinterpret_cast<uint32_t*>(dsm + ASH_BYTES);

    const int tid  = threadIdx.x;
    const int lane = tid & 31;
    const int wid  = tid >> 5;
    const int b    = blockIdx.z;
    const int y0   = blockIdx.y << 3;
    const int x0   = blockIdx.x << 4;

    // ---- load 10x18 px halo (HWC fp16), zero-padded at borders ----
    {
        const __half* src_b = g_hwc + (size_t)b * (512 * 512 * 64);
        for (int idx = tid; idx < 1440; idx += 256) {       // 180 px * 8 chunks
            const int p  = idx >> 3;
            const int ck = idx & 7;
            const int r  = p / 18;
            const int c  = p - r * 18;
            const int gy = y0 - 1 + r;
            const int gx = x0 - 1 + c;
            uint4 v = make_uint4(0u, 0u, 0u, 0u);
            if ((unsigned)gy < 512u && (unsigned)gx < 512u)
                v = *reinterpret_cast<const uint4*>(
                        src_b + ((size_t)gy * 512 + gx) * 64 + ck * 8);
            *reinterpret_cast<uint4*>(Ash + p * 72 + ck * 8) = v;
        }
    }
    // ---- load B: 288x64 uint32 -> smem rows padded to 72 ----
    {
        const uint4* src = reinterpret_cast<const uint4*>(g_wB + (size_t)b * 18432);
        for (int idx = tid; idx < 4608; idx += 256) {
            const int row = idx >> 4;
            const int c4  = idx & 15;
            *reinterpret_cast<uint4*>(Bsh + row * 72 + c4 * 4) = src[idx];
        }
    }
    __syncthreads();

    const int wm = wid & 3;    // m: tile rows 2wm, 2wm+1
    const int wn = wid >> 2;   // n: o range [wn*32, wn*32+32)

    float acc[2][4][4];
    #pragma unroll
    for (int mi = 0; mi < 2; mi++)
        #pragma unroll
        for (int ni = 0; ni < 4; ni++)
            #pragma unroll
            for (int j = 0; j < 4; j++) acc[mi][ni][j] = 0.f;

    // ldmatrix lane addresses: row = pixel x-offset (lane&15), col-half = lane>>4.
    const uint32_t ashu = smem_u32(Ash);
    uint32_t aAddr[2];
    #pragma unroll
    for (int mi = 0; mi < 2; mi++)
        aAddr[mi] = ashu + (uint32_t)(((2 * wm + mi) * 18 + (lane & 15)) * 144)
                         + (uint32_t)((lane >> 4) * 16);

    // B lane base (word index): rows t=lane&3, col = wn*32 + (lane>>2) (+ni*8)
    const uint32_t* Blane = Bsh + (lane & 3) * 72 + wn * 32 + (lane >> 2);

    #pragma unroll
    for (int tap = 0; tap < 9; tap++) {
        const uint32_t aoff = (uint32_t)(((tap / 3) * 18 + (tap % 3)) * 144);
        #pragma unroll
        for (int kc = 0; kc < 4; kc++) {
            uint32_t a[2][4];
            #pragma unroll
            for (int mi = 0; mi < 2; mi++)
                asm volatile(
                    "ldmatrix.sync.aligned.m8n8.x4.shared.b16 {%0,%1,%2,%3}, [%4];"
                    : "=r"(a[mi][0]), "=r"(a[mi][1]), "=r"(a[mi][2]), "=r"(a[mi][3])
                    : "r"(aAddr[mi] + aoff + (uint32_t)(kc * 32)));

            const int ks = tap * 4 + kc;                 // K16-step index
            const uint32_t* Brow = Blane + ks * 8 * 72;  // kpair rows ks*8 .. ks*8+7
            #pragma unroll
            for (int ni = 0; ni < 4; ni++) {
                const uint32_t b0 = Brow[ni * 8];            // kpairs +0..3
                const uint32_t b1 = Brow[ni * 8 + 4 * 72];   // kpairs +4..7
                #pragma unroll
                for (int mi = 0; mi < 2; mi++)
                    asm volatile(
                        "mma.sync.aligned.m16n8k16.row.col.f32.f16.f16.f32 "
                        "{%0,%1,%2,%3}, {%4,%5,%6,%7}, {%8,%9}, {%0,%1,%2,%3};"
                        : "+f"(acc[mi][ni][0]), "+f"(acc[mi][ni][1]),
                          "+f"(acc[mi][ni][2]), "+f"(acc[mi][ni][3])
                        : "r"(a[mi][0]), "r"(a[mi][1]), "r"(a[mi][2]), "r"(a[mi][3]),
                          "r"(b0), "r"(b1));
            }
        }
    }

    // ---- epilogue: c0,c1 -> (x, o), (x, o+1); c2,c3 -> (x+8, o), (x+8, o+1) ----
    const int xg = x0 + (lane >> 2);
    const int og = wn * 32 + 2 * (lane & 3);
    #pragma unroll
    for (int mi = 0; mi < 2; mi++) {
        const int y = y0 + 2 * wm + mi;
        #pragma unroll
        for (int ni = 0; ni < 4; ni++) {
            float* p = out + ((size_t)(b * 64 + og + ni * 8) << 18)
                           + ((size_t)y << 9) + xg;
            p[0]               = acc[mi][ni][0];
            p[(size_t)1 << 18] = acc[mi][ni][1];
            p[8]               = acc[mi][ni][2];
            p[((size_t)1 << 18) + 8] = acc[mi][ni][3];
        }
    }
}

// ---------------------------------------------------------------------------
// Harness entry point.
//   d_in[0] = input  (4, 64, 512, 512) float
//   d_in[1] = style  (4, 64)           float
//   d_in[2] = weight (64, 64, 3, 3)    float
//   d_out   = (4, 64, 512, 512) float
// ---------------------------------------------------------------------------
extern "C" void kernel_launch(void* const* d_in, const int* in_sizes, int n_in,
                              void* d_out, int out_size) {
    const float* input  = (const float*)d_in[0];
    const float* style  = (const float*)d_in[1];
    const float* weight = (const float*)d_in[2];
    float* out = (float*)d_out;

    cudaFuncSetAttribute(conv_kernel, cudaFuncAttributeMaxDynamicSharedMemorySize,
                         CONV_SMEM);

    modulate_kernel<<<256, 256>>>(weight, style);
    transpose_kernel<<<dim3(4, 512, 4), 256>>>(input);
    conv_kernel<<<dim3(32, 64, 4), 256, CONV_SMEM>>>(out);
}